// round 12
// baseline (speedup 1.0000x reference)
#include <cuda_runtime.h>
#include <cstdint>

#define N_      2048
#define T_      512
#define B_      32
#define NCTA    256
#define NLOC    8           // neurons per CTA
#define NTHR    256
#define CJ      128         // A j-chunk size
#define NCHUNK  16
#define RP      36          // padded row stride (floats) = 144B
#define NSLOT   4

#define DT_     1e-4f
#define U_C     0.3f
#define TAU_    0.008f
#define TAU_F   1.5f
#define TAU_D   0.3f
#define ALPHA_  1.5f
#define I_B_    8.0f
#define J_EI_   1.1f
#define J_IE_   2.2f

// output layout: tuple (all_h, all_u, all_x, all_hI, outputs) concatenated
#define OFF_H   ((size_t)0)
#define OFF_U   ((size_t)T_ * B_ * N_)
#define OFF_X   ((size_t)2 * T_ * B_ * N_)
#define OFF_HI  ((size_t)3 * T_ * B_ * N_)
#define OFF_OUT (OFF_HI + (size_t)T_ * B_)

// ---- static device scratch ----
__device__ __align__(128) float g_A[2][N_ * B_];     // u*x*R, [j][b]
__device__ __align__(128) float g_pR[2][B_ * NCTA];  // transposed: [b][cta]
__device__ __align__(128) float g_pO[2][B_ * NCTA];  // transposed: [b][cta]
__device__ unsigned int g_bar  = 0;
__device__ unsigned int g_exit = 0;

// smem layout (floats)
#define SLOT_F      (16 * RP)                 // 576
#define SLOT_BYTES  (SLOT_F * 4)              // 2304
#define WT_F        (NSLOT * SLOT_F)          // 2304
#define SM_PART     (8 * WT_F)                // 18432 (8 warps)
#define SMEM_FLOATS (SM_PART + 128 * RP + 16) // + 4608 + 16
#define SMEM_BYTES  (SMEM_FLOATS * 4)         // 92224 B  (2 CTAs/SM fit)

__device__ __forceinline__ float rate_fn(float h) {
    float z  = h * (1.0f / ALPHA_);
    float sp = fmaxf(z, 0.0f) + log1pf(__expf(-fabsf(z)));
    return ALPHA_ * sp;
}

// ---- packed f32x2 helpers ----
__device__ __forceinline__ unsigned long long pack2(float v) {
    unsigned long long r;
    asm("mov.b64 %0, {%1, %1};" : "=l"(r) : "f"(v));
    return r;
}
__device__ __forceinline__ void fma2(unsigned long long& d,
                                     unsigned long long a,
                                     unsigned long long b) {
    asm("fma.rn.f32x2 %0, %1, %2, %0;" : "+l"(d) : "l"(a), "l"(b));
}
__device__ __forceinline__ unsigned long long add2(unsigned long long a,
                                                   unsigned long long b) {
    unsigned long long r;
    asm("add.rn.f32x2 %0, %1, %2;" : "=l"(r) : "l"(a), "l"(b));
    return r;
}

// ---- cp.async helpers ----
__device__ __forceinline__ void cp_async16(uint32_t smem_addr, const void* gptr) {
    asm volatile("cp.async.cg.shared.global [%0], [%1], 16;"
                 :: "r"(smem_addr), "l"(gptr));
}
__device__ __forceinline__ void cp_commit() {
    asm volatile("cp.async.commit_group;");
}
template <int NKeep>
__device__ __forceinline__ void cp_wait() {
    asm volatile("cp.async.wait_group %0;" :: "n"(NKeep));
}

__global__ void __launch_bounds__(NTHR, 2)
stp_kernel(const float* __restrict__ inp,    // [T,B,1]
           const float* __restrict__ W_in,   // [N,1]
           const float* __restrict__ J,      // [N,N]
           const float* __restrict__ W_out,  // [1,N]
           float* __restrict__ out)
{
    extern __shared__ float sm[];
    float* part = sm + SM_PART;   // [128][RP]

    const int tid  = threadIdx.x;
    const int cta  = blockIdx.x;
    const int il   = tid & 7;           // local neuron 0..7  (lane bits 0..2)
    const int s    = tid >> 3;          // j-slice 0..31 == batch b
    const int b    = s;
    const int lane = tid & 31;
    const int warp = tid >> 5;          // 0..7, owns s in {4w..4w+3}
    const int sl   = s & 3;             // s within warp
    const int i    = cta * NLOC + il;   // global neuron
    const int c0   = cta & 15;          // chunk rotation

    float* warpTile = sm + warp * WT_F;
    const uint32_t wt_base = (uint32_t)__cvta_generic_to_shared(warpTile);

    // staging map: 4 cp.async16 per thread cover warp's 16 rows x 128B per chunk
    int goff[4], soff[4];
    #pragma unroll
    for (int o = 0; o < 4; ++o) {
        int n   = o * 32 + lane;
        int row = n >> 3;                              // 0..15
        int seg = n & 7;                               // 16B segment
        int jin = (row >> 2) * 32 + 4 * warp + (row & 3);  // j within chunk
        goff[o] = jin * B_ + seg * 4;                  // floats
        soff[o] = (row * RP + seg * 4) * 4;            // bytes within slot
    }

    // ---- this thread's 64 J coefficients in chunk-iteration order ----
    float Jreg[64];
    {
        const float* Jrow = J + (size_t)i * N_;
        #pragma unroll
        for (int cc = 0; cc < NCHUNK; ++cc) {
            const int c = (c0 + cc) & 15;
            #pragma unroll
            for (int q = 0; q < 4; ++q)
                Jreg[cc * 4 + q] = __ldg(&Jrow[c * CJ + q * 32 + s]);
        }
    }

    // ---- init state ----
    float h = 0.0f, u = U_C, x = 1.0f, hI = 0.0f;
    const float wi = __ldg(&W_in[i]);
    const float wo = __ldg(&W_out[i]);

    // ---- publish A0, pR0 ----
    float Rcur = rate_fn(h);
    {
        __stcg(&g_A[0][(size_t)i * B_ + b], u * x * Rcur);
        float sR = Rcur;
        #pragma unroll
        for (int o = 1; o <= 4; o <<= 1) sR += __shfl_xor_sync(0xffffffffu, sR, o);
        if (il == 0) __stcg(&g_pR[0][b * NCTA + cta], sR);
    }
    __syncthreads();
    if (tid == 0) {
        __threadfence();
        atomicAdd(&g_bar, 1u);
        while (*(volatile unsigned int*)&g_bar < (unsigned)NCTA) { }
        __threadfence();
    }
    __syncthreads();

    for (int t = 0; t < T_; ++t) {
        const int buf  = t & 1;
        const int nbuf = buf ^ 1;
        const float* gA = g_A[buf];

        auto stage = [&](int cc) {
            const int chunk = (c0 + cc) & 15;
            const float* src = gA + chunk * (CJ * B_);
            const uint32_t sb = wt_base + (uint32_t)((cc & 3) * SLOT_BYTES);
            #pragma unroll
            for (int o = 0; o < 4; ++o)
                cp_async16(sb + (uint32_t)soff[o], src + goff[o]);
            cp_commit();
        };

        stage(0); stage(1); stage(2);
        const float inval = __ldg(&inp[t * B_ + b]);

        unsigned long long acc2[16];
        #pragma unroll
        for (int m = 0; m < 16; ++m) acc2[m] = 0ull;

        #pragma unroll
        for (int cc = 0; cc < NCHUNK; ++cc) {
            if (cc + 3 < NCHUNK) stage(cc + 3);
            if      (cc < NCHUNK - 3) cp_wait<3>();
            else if (cc == NCHUNK - 3) cp_wait<2>();
            else if (cc == NCHUNK - 2) cp_wait<1>();
            else                       cp_wait<0>();
            __syncwarp();

            const float* Ab = warpTile + (cc & 3) * SLOT_F;
            #pragma unroll
            for (int q = 0; q < 4; ++q) {
                unsigned long long jp = pack2(Jreg[cc * 4 + q]);
                const ulonglong2* a8 = (const ulonglong2*)(Ab + (q * 4 + sl) * RP);
                #pragma unroll
                for (int e = 0; e < 8; ++e) {
                    ulonglong2 v = a8[e];
                    fma2(acc2[2 * e],     v.x, jp);
                    fma2(acc2[2 * e + 1], v.y, jp);
                }
            }
        }

        // --- combine s with s^2 (lane xor 16), dump 16 s-classes to part ---
        #pragma unroll
        for (int m = 0; m < 16; ++m) {
            unsigned long long o = __shfl_xor_sync(0xffffffffu, acc2[m], 16);
            acc2[m] = add2(acc2[m], o);
        }
        if ((s & 2) == 0) {
            const int k = (s >> 2) * 2 + (s & 1);      // 0..15
            ulonglong2* dst = (ulonglong2*)(part + (k * 8 + il) * RP);
            #pragma unroll
            for (int m = 0; m < 8; ++m)
                dst[m] = make_ulonglong2(acc2[2 * m], acc2[2 * m + 1]);
        }
        __syncthreads();

        // --- cross-CTA pR/pO gather (coalesced float4, overlaps part gather) ---
        const float4* pR4 = (const float4*)&g_pR[buf][b * NCTA + il * 32];
        float4 rv[8];
        #pragma unroll
        for (int k = 0; k < 8; ++k) rv[k] = __ldcg(&pR4[k]);
        float4 ov0 = make_float4(0.f, 0.f, 0.f, 0.f);
        float sumO = 0.0f;
        if (cta == 0) {
            const float4* pO4 = (const float4*)&g_pO[buf][b * NCTA + il * 32];
            #pragma unroll
            for (int k = 0; k < 8; ++k) {
                float4 v = __ldcg(&pO4[k]);
                sumO += v.x + v.y + v.z + v.w;
            }
            (void)ov0;
        }

        // --- gather syn: thread (il, b) sums 16 k-classes ---
        float syn = 0.0f;
        #pragma unroll
        for (int k = 0; k < 16; ++k)
            syn += part[(k * 8 + il) * RP + b];

        float sumR = 0.0f;
        #pragma unroll
        for (int k = 0; k < 8; ++k)
            sumR += rv[k].x + rv[k].y + rv[k].z + rv[k].w;
        #pragma unroll
        for (int o = 1; o <= 4; o <<= 1)
            sumR += __shfl_xor_sync(0xffffffffu, sumR, o);
        if (cta == 0) {
            #pragma unroll
            for (int o = 1; o <= 4; o <<= 1)
                sumO += __shfl_xor_sync(0xffffffffu, sumO, o);
            if (t > 0 && il == 0)
                out[OFF_OUT + (size_t)(t - 1) * B_ + b] = sumO;
        }

        // --- state update ---
        float Ie  = inval * wi;
        float RI  = rate_fn(hI);
        float dh  = (-h + syn + I_B_ + Ie) * (1.0f / TAU_) - J_EI_ * RI * (1.0f / TAU_);
        float du  = (U_C - u) * (1.0f / TAU_F) + U_C * (1.0f - u) * Rcur;
        float dx  = (1.0f - x) * (1.0f / TAU_D) - u * x * Rcur;
        float dhI = (-hI + J_IE_ * sumR) * (1.0f / TAU_);
        h  += dh  * DT_;
        u  += du  * DT_;
        x  += dx  * DT_;
        hI += dhI * DT_;

        // --- publish next-step activation + partials ---
        Rcur = rate_fn(h);
        {
            __stcg(&g_A[nbuf][(size_t)i * B_ + b], u * x * Rcur);
            float sR = Rcur;
            float sO = Rcur * wo;
            #pragma unroll
            for (int o = 1; o <= 4; o <<= 1) {
                sR += __shfl_xor_sync(0xffffffffu, sR, o);
                sO += __shfl_xor_sync(0xffffffffu, sO, o);
            }
            if (il == 0) {
                __stcg(&g_pR[nbuf][b * NCTA + cta], sR);
                __stcg(&g_pO[nbuf][b * NCTA + cta], sO);
            }
        }

        // --- barrier: arrive early, overlap output writes with propagation ---
        __syncthreads();
        if (tid == 0) {
            __threadfence();
            atomicAdd(&g_bar, 1u);
        }
        const size_t row = (size_t)(t * B_ + b) * N_ + i;
        __stcs(&out[OFF_H + row], h);
        __stcs(&out[OFF_U + row], u);
        __stcs(&out[OFF_X + row], x);
        if (cta == 0 && il == 0)
            out[OFF_HI + (size_t)t * B_ + b] = hI;
        if (tid == 0) {
            while (*(volatile unsigned int*)&g_bar < (unsigned)NCTA * (unsigned)(t + 2)) { }
            __threadfence();
        }
        __syncthreads();
    }

    // --- final outputs[T-1] (CTA 0); pO published into buffer 0 at t=511 ---
    if (cta == 0) {
        const float4* pO4 = (const float4*)&g_pO[0][b * NCTA + il * 32];
        float so = 0.0f;
        #pragma unroll
        for (int k = 0; k < 8; ++k) {
            float4 v = __ldcg(&pO4[k]);
            so += v.x + v.y + v.z + v.w;
        }
        #pragma unroll
        for (int o = 1; o <= 4; o <<= 1)
            so += __shfl_xor_sync(0xffffffffu, so, o);
        if (il == 0)
            out[OFF_OUT + (size_t)(T_ - 1) * B_ + b] = so;
    }

    // --- reset barrier counter for CUDA-graph replays ---
    __syncthreads();
    if (tid == 0) {
        __threadfence();
        unsigned v = atomicAdd(&g_exit, 1u);
        if (v == NCTA - 1) {
            g_bar  = 0;
            g_exit = 0;
            __threadfence();
        }
    }
}

extern "C" void kernel_launch(void* const* d_in, const int* in_sizes, int n_in,
                              void* d_out, int out_size) {
    const float* inp   = (const float*)d_in[0];
    const float* W_in  = (const float*)d_in[1];
    const float* J     = (const float*)d_in[2];
    const float* W_out = (const float*)d_in[3];
    float* out = (float*)d_out;

    static bool attr_done = false;
    if (!attr_done) {
        cudaFuncSetAttribute(stp_kernel,
                             cudaFuncAttributeMaxDynamicSharedMemorySize,
                             SMEM_BYTES);
        attr_done = true;
    }
    stp_kernel<<<NCTA, NTHR, SMEM_BYTES>>>(inp, W_in, J, W_out, out);
}

// round 14
// speedup vs baseline: 2.7397x; 2.7397x over previous
#include <cuda_runtime.h>
#include <cstdint>

#define N_    2048
#define T_    512
#define B_    32
#define NCTA  128
#define NLOC  16
#define NTHR  512

#define DT_    1e-4f
#define U_C    0.3f
#define TAU_   0.008f
#define TAU_F  1.5f
#define TAU_D  0.3f
#define ALPHA_ 1.5f
#define I_B_   8.0f
#define J_EI_  1.1f
#define J_IE_  2.2f

// output layout: tuple (all_h, all_u, all_x, all_hI, outputs) concatenated
#define OFF_H   ((size_t)0)
#define OFF_U   ((size_t)T_ * B_ * N_)
#define OFF_X   ((size_t)2 * T_ * B_ * N_)
#define OFF_HI  ((size_t)3 * T_ * B_ * N_)
#define OFF_OUT (OFF_HI + (size_t)T_ * B_)

// ---- static device scratch ----
// Activations in MMA-fragment-major layout (tf32-rounded), double buffered.
// Slot of value A[j][b]:
//   float index = (j>>5)*1024 + (b>>3)*256 + ((j>>2)&1)*128 + ((b&7)*4 + (j&3))*4 + ((j>>3)&3)
__device__ __align__(128) float g_AF[2][N_ * B_];
__device__ __align__(128) float g_pR[2][B_ * NCTA];   // [b][cta]
__device__ __align__(128) float g_pO[2][B_ * NCTA];   // [b][cta]
__device__ unsigned g_bar = 0, g_exit = 0;

__device__ __forceinline__ float rate_fn(float h) {
    float z = h * (1.0f / ALPHA_);
    return ALPHA_ * (fmaxf(z, 0.0f) + log1pf(__expf(-fabsf(z))));
}
__device__ __forceinline__ float tf32r(float v) {
    uint32_t r;
    asm("cvt.rna.tf32.f32 %0, %1;" : "=r"(r) : "f"(v));
    return __uint_as_float(r);
}
__device__ __forceinline__ void mma8(float* c, uint32_t a0, uint32_t a1,
                                     uint32_t a2, uint32_t a3,
                                     uint32_t b0, uint32_t b1) {
    asm volatile(
        "mma.sync.aligned.m16n8k8.row.col.f32.tf32.tf32.f32 "
        "{%0,%1,%2,%3}, {%4,%5,%6,%7}, {%8,%9}, {%0,%1,%2,%3};"
        : "+f"(c[0]), "+f"(c[1]), "+f"(c[2]), "+f"(c[3])
        : "r"(a0), "r"(a1), "r"(a2), "r"(a3), "r"(b0), "r"(b1));
}
__device__ __forceinline__ int af_idx(int j, int b) {
    return ((j >> 5) << 10) + ((b >> 3) << 8) + (((j >> 2) & 1) << 7)
         + ((((b & 7) << 2) + (j & 3)) << 2) + ((j >> 3) & 3);
}

__global__ void __launch_bounds__(NTHR, 1)
stp_kernel(const float* __restrict__ inp,    // [T,B,1]
           const float* __restrict__ W_in,   // [N,1]
           const float* __restrict__ J,      // [N,N]
           const float* __restrict__ W_out,  // [1,N]
           float* __restrict__ out)
{
    __shared__ float part[16 * 16 * 34];     // [warp][i_local][b] padded

    const int tid  = threadIdx.x;
    const int cta  = blockIdx.x;
    const int il   = tid & 15;               // local neuron (state role)
    const int b    = tid >> 4;               // batch (state role)
    const int lane = tid & 31;
    const int warp = tid >> 5;               // k-slice: j in [warp*128, warp*128+128)
    const int g    = lane >> 2;              // mma row/col group
    const int tg   = lane & 3;               // mma thread-in-group
    const int i0   = cta * NLOC;
    const int i    = i0 + il;                // neuron this thread updates

    // ---- J A-fragments (tf32), loaded once: 64 regs/thread ----
    uint32_t Ja[16][4];
    {
        #pragma unroll
        for (int jt = 0; jt < 16; ++jt) {
            const int j0 = warp * 128 + jt * 8;
            Ja[jt][0] = __float_as_uint(tf32r(__ldg(&J[(size_t)(i0 + g)     * N_ + j0 + tg])));
            Ja[jt][1] = __float_as_uint(tf32r(__ldg(&J[(size_t)(i0 + g + 8) * N_ + j0 + tg])));
            Ja[jt][2] = __float_as_uint(tf32r(__ldg(&J[(size_t)(i0 + g)     * N_ + j0 + tg + 4])));
            Ja[jt][3] = __float_as_uint(tf32r(__ldg(&J[(size_t)(i0 + g + 8) * N_ + j0 + tg + 4])));
        }
    }

    // ---- init state ----
    float h = 0.0f, u = U_C, x = 1.0f, hI = 0.0f;
    const float wi  = __ldg(&W_in[i]);
    const float wo  = __ldg(&W_out[i]);
    const int   afo = af_idx(i, b);          // this thread's publish slot

    // ---- publish A0, pR0 ----
    float Rcur = rate_fn(h);
    __stcg(&g_AF[0][afo], tf32r(u * x * Rcur));
    {
        float sR = Rcur;
        #pragma unroll
        for (int o = 1; o <= 8; o <<= 1) sR += __shfl_xor_sync(0xffffffffu, sR, o);
        if (il == 0) __stcg(&g_pR[0][b * NCTA + cta], sR);
    }
    __threadfence();
    __syncthreads();
    if (tid == 0) {
        atomicAdd(&g_bar, 1u);
        while (*(volatile unsigned*)&g_bar < (unsigned)NCTA) { }
        __threadfence();
    }
    __syncthreads();

    for (int t = 0; t < T_; ++t) {
        const int buf  = t & 1;
        const int nbuf = buf ^ 1;

        // ---- MMA: D[16 i x 32 b] partial over this warp's 128-j slice ----
        float c[4][4];
        #pragma unroll
        for (int bt = 0; bt < 4; ++bt)
            #pragma unroll
            for (int e = 0; e < 4; ++e) c[bt][e] = 0.0f;

        const float4* AF4 = (const float4*)g_AF[buf];
        #pragma unroll
        for (int q = 0; q < 4; ++q) {
            const int base = (warp * 4 + q) * 256 + lane;
            #pragma unroll
            for (int bt = 0; bt < 4; ++bt) {
                float4 B0 = __ldcg(&AF4[base + bt * 64]);
                float4 B1 = __ldcg(&AF4[base + bt * 64 + 32]);
                mma8(c[bt], Ja[q*4+0][0], Ja[q*4+0][1], Ja[q*4+0][2], Ja[q*4+0][3],
                     __float_as_uint(B0.x), __float_as_uint(B1.x));
                mma8(c[bt], Ja[q*4+1][0], Ja[q*4+1][1], Ja[q*4+1][2], Ja[q*4+1][3],
                     __float_as_uint(B0.y), __float_as_uint(B1.y));
                mma8(c[bt], Ja[q*4+2][0], Ja[q*4+2][1], Ja[q*4+2][2], Ja[q*4+2][3],
                     __float_as_uint(B0.z), __float_as_uint(B1.z));
                mma8(c[bt], Ja[q*4+3][0], Ja[q*4+3][1], Ja[q*4+3][2], Ja[q*4+3][3],
                     __float_as_uint(B0.w), __float_as_uint(B1.w));
            }
        }

        // ---- cross-CTA pR/pO gathers (L2 latency overlaps part reduce) ----
        float rv[8];
        #pragma unroll
        for (int q = 0; q < 8; ++q)
            rv[q] = __ldcg(&g_pR[buf][b * NCTA + il * 8 + q]);
        float sumO = 0.0f;
        if (cta == 0) {
            #pragma unroll
            for (int q = 0; q < 8; ++q)
                sumO += __ldcg(&g_pO[buf][b * NCTA + il * 8 + q]);
        }

        // ---- dump D fragments: part[warp][i_local][b] ----
        {
            float* pw = part + warp * 544;
            #pragma unroll
            for (int bt = 0; bt < 4; ++bt) {
                *(float2*)&pw[g * 34 + bt * 8 + 2 * tg]       = make_float2(c[bt][0], c[bt][1]);
                *(float2*)&pw[(g + 8) * 34 + bt * 8 + 2 * tg] = make_float2(c[bt][2], c[bt][3]);
            }
        }
        __syncthreads();

        // ---- syn: sum 16 k-slice partials ----
        float syn = 0.0f;
        #pragma unroll
        for (int w = 0; w < 16; ++w)
            syn += part[w * 544 + il * 34 + b];

        float sumR = rv[0]+rv[1]+rv[2]+rv[3]+rv[4]+rv[5]+rv[6]+rv[7];
        #pragma unroll
        for (int o = 1; o <= 8; o <<= 1)
            sumR += __shfl_xor_sync(0xffffffffu, sumR, o);
        if (cta == 0) {
            #pragma unroll
            for (int o = 1; o <= 8; o <<= 1)
                sumO += __shfl_xor_sync(0xffffffffu, sumO, o);
            if (t > 0 && il == 0)
                out[OFF_OUT + (size_t)(t - 1) * B_ + b] = sumO;
        }

        // ---- state update ----
        float Ie  = __ldg(&inp[t * B_ + b]) * wi;
        float RI  = rate_fn(hI);
        float dh  = (-h + syn + I_B_ + Ie) * (1.0f / TAU_) - J_EI_ * RI * (1.0f / TAU_);
        float du  = (U_C - u) * (1.0f / TAU_F) + U_C * (1.0f - u) * Rcur;
        float dx  = (1.0f - x) * (1.0f / TAU_D) - u * x * Rcur;
        float dhI = (-hI + J_IE_ * sumR) * (1.0f / TAU_);
        h += dh * DT_; u += du * DT_; x += dx * DT_; hI += dhI * DT_;

        // ---- publish next-step activation + partials ----
        Rcur = rate_fn(h);
        __stcg(&g_AF[nbuf][afo], tf32r(u * x * Rcur));
        {
            float sR = Rcur, sO = Rcur * wo;
            #pragma unroll
            for (int o = 1; o <= 8; o <<= 1) {
                sR += __shfl_xor_sync(0xffffffffu, sR, o);
                sO += __shfl_xor_sync(0xffffffffu, sO, o);
            }
            if (il == 0) {
                __stcg(&g_pR[nbuf][b * NCTA + cta], sR);
                __stcg(&g_pO[nbuf][b * NCTA + cta], sO);
            }
        }

        // ---- grid barrier: arrive early, overlap output writes ----
        __threadfence();
        __syncthreads();                     // publishes done + part WAR
        if (tid == 0) atomicAdd(&g_bar, 1u);
        const size_t row = (size_t)(t * B_ + b) * N_ + i;
        __stcs(&out[OFF_H + row], h);
        __stcs(&out[OFF_U + row], u);
        __stcs(&out[OFF_X + row], x);
        if (cta == 0 && il == 0)
            out[OFF_HI + (size_t)t * B_ + b] = hI;
        if (tid == 0) {
            while (*(volatile unsigned*)&g_bar < (unsigned)NCTA * (unsigned)(t + 2)) { }
            __threadfence();
        }
        __syncthreads();
    }

    // ---- outputs[T-1] (published into buffer 0 at t = 511) ----
    if (cta == 0) {
        float so = 0.0f;
        #pragma unroll
        for (int q = 0; q < 8; ++q)
            so += __ldcg(&g_pO[0][b * NCTA + il * 8 + q]);
        #pragma unroll
        for (int o = 1; o <= 8; o <<= 1)
            so += __shfl_xor_sync(0xffffffffu, so, o);
        if (il == 0)
            out[OFF_OUT + (size_t)(T_ - 1) * B_ + b] = so;
    }

    // ---- reset barrier counter for CUDA-graph replays ----
    __syncthreads();
    if (tid == 0) {
        __threadfence();
        unsigned v = atomicAdd(&g_exit, 1u);
        if (v == NCTA - 1) { g_bar = 0; g_exit = 0; __threadfence(); }
    }
}

extern "C" void kernel_launch(void* const* d_in, const int* in_sizes, int n_in,
                              void* d_out, int out_size) {
    const float* inp   = (const float*)d_in[0];
    const float* W_in  = (const float*)d_in[1];
    const float* J     = (const float*)d_in[2];
    const float* W_out = (const float*)d_in[3];
    float* out = (float*)d_out;

    stp_kernel<<<NCTA, NTHR>>>(inp, W_in, J, W_out, out);
}